// round 13
// baseline (speedup 1.0000x reference)
#include <cuda_runtime.h>
#include <math.h>

#define G        512
#define S        32
#define PTS      8
#define SEGS_PER (PTS - 1)           // 7
#define NSEG     (S * SEGS_PER)      // 224
#define TILE     16
#define NTHREADS 256                 // 1 px/thread, 8 warps/CTA
#define TPR      (G / TILE)          // 32 tiles per row -> 1024 CTAs

__device__ __forceinline__ float fast_sqrt(float x) {
    float r;
    asm("sqrt.approx.f32 %0, %1;" : "=f"(r) : "f"(x));
    return r;
}

// ---------------------------------------------------------------------------
// One 16x16 tile per 256-thread CTA (1024 CTAs, single wave).
// Cull: single round - thread t < 224 owns segment t (points + thickness
//   preloaded before the first barrier; out-of-range lanes carry sentinels
//   that self-cull). Warp-ballot compaction, <=7 shared atomics total.
//   Survivor record: (vx,vy,ex,ey) + (fx,fy,sc,-), fx,fy = e*invd2 so the
//   render-time frac is two fma, no divide/multiply.
// Render: 1 pixel/thread over ~7 survivors; min of scaled squared distance
//   (min is monotone under sqrt); one MUFU sqrt.approx; coalesced store.
// ---------------------------------------------------------------------------
__global__ void __launch_bounds__(NTHREADS)
render_kernel(const float* __restrict__ strokes,
              const float* __restrict__ thick,
              float* __restrict__ out) {
    __shared__ float4 s_a[NSEG];     // vx, vy, ex, ey
    __shared__ float4 s_b[NSEG];     // fx, fy, sc, pad
    __shared__ int    s_n;

    const int tid  = threadIdx.x;
    const int lane = tid & 31;

    // ---- Preload cull data (latency hides under the first barrier) ----
    float2 p0 = make_float2(1e9f, 1e9f), p1 = p0;
    float  tk = 0.0f;
    if (tid < NSEG) {
        int s = (tid * 9363) >> 16;              // tid / 7
        int i = s * PTS + (tid - s * SEGS_PER);  // point index
        p0 = ((const float2*)strokes)[i];
        p1 = ((const float2*)strokes)[i + 1];
        tk = thick[s];
    }
    if (tid == 0) s_n = 0;
    __syncthreads();

    const int ti = blockIdx.y * TILE;            // row base (out stride G)
    const int tj = blockIdx.x * TILE;            // col base (contiguous)

    const float cx   = (float)ti + (TILE - 1) * 0.5f;
    const float cy   = (float)tj + (TILE - 1) * 0.5f;
    const float RMAX = (TILE - 1) * 0.5f * 1.41421356f + 1.0f;

    // ---- Cull: one round, ballot compaction ----
    {
        float vx = __saturatef(p0.x) * (float)G;
        float vy = __saturatef(p0.y) * (float)G;
        float wx = __saturatef(p1.x) * (float)G;
        float wy = __saturatef(p1.y) * (float)G;
        if (p0.x > 2.0f) { vx = 1e9f; vy = 1e9f; wx = 1e9f; wy = 1e9f; }

        float ex = wx - vx;
        float ey = wy - vy;
        float d2 = ex * ex + ey * ey;
        float invd2 = __fdividef(1.0f, d2 + 1e-5f);
        float t  = fmaxf(fmaf(tk, 2.0f, 0.5f), 0.5f);
        float rr = 2.0f * t;

        float dx  = cx - vx;
        float dy  = cy - vy;
        float dot = dx * ex + dy * ey;
        float fr  = __saturatef(dot * invd2);
        float ddx = fmaf(-fr, ex, dx);
        float ddy = fmaf(-fr, ey, dy);
        float dq  = ddx * ddx + ddy * ddy;
        float thr = rr + RMAX;
        bool keep = (dq <= thr * thr);

        unsigned bal = __ballot_sync(0xffffffffu, keep);
        int base = 0;
        if (lane == 0 && bal) base = atomicAdd(&s_n, __popc(bal));
        base = __shfl_sync(0xffffffffu, base, 0);
        if (keep) {
            int p = base + __popc(bal & ((1u << lane) - 1u));
            s_a[p] = make_float4(vx, vy, ex, ey);
            s_b[p] = make_float4(ex * invd2, ey * invd2,
                                 __fdividef(1.0f, rr * rr), 0.0f);
        }
    }
    __syncthreads();

    // ---- Render: 1 pixel per thread ----
    const int tx = tid & (TILE - 1);             // col 0..15
    const int ty = tid >> 4;                     // row 0..15
    const float px = (float)(ti + ty);
    const float py = (float)(tj + tx);
    const int n = s_n;

    float m = 1e30f;
    #pragma unroll 2
    for (int q = 0; q < n; q++) {
        float4 a = s_a[q];                       // vx vy ex ey
        float4 b = s_b[q];                       // fx fy sc -
        float dx = px - a.x;
        float dy = py - a.y;
        float fr = __saturatef(fmaf(dx, b.x, dy * b.y));
        float ddx = fmaf(-fr, a.z, dx);
        float ddy = fmaf(-fr, a.w, dy);
        float dq  = fmaf(ddx, ddx, ddy * ddy);
        m = fminf(m, dq * b.z);
    }

    out[(ti + ty) * G + (tj + tx)] = fminf(fast_sqrt(m), 1.0f);
}

extern "C" void kernel_launch(void* const* d_in, const int* in_sizes, int n_in,
                              void* d_out, int out_size) {
    // metadata order: strokes [32,8,2] f32 (512 elems), thicknesses [32] f32.
    const float* strokes = (const float*)d_in[0];
    const float* thick   = (const float*)d_in[1];
    if (n_in >= 2 && in_sizes[0] == S && in_sizes[1] == S * PTS * 2) {
        strokes = (const float*)d_in[1];
        thick   = (const float*)d_in[0];
    }
    float* out = (float*)d_out;

    dim3 block(NTHREADS);
    dim3 grid(TPR, TPR);
    render_kernel<<<grid, block>>>(strokes, thick, out);
}